// round 16
// baseline (speedup 1.0000x reference)
#include <cuda_runtime.h>
#include <cuda_bf16.h>
#include <cstdint>

// out[i] = 0.1 * x[i] * sum_j A[i][j] * (1 - x[j])
// HBM-bound fp32 matvec. A (1 GiB) streamed once with evict-first LDG.128.
// K-split SEG=8: one warp per (row, 1/8-row segment) -> 8 KB tasks,
// independent warp exits + atomicAdd. MLP=8 front-batched loads.
// 512-thread blocks (16 warps): 2 CTAs/SM at 56 regs -> 32 warps/SM.
// Zero-init kernel overlapped with the matvec via PDL.

#define WARPS_PER_BLOCK 16
#define THREADS (WARPS_PER_BLOCK * 32)
#define SEG 8

__global__ void init_out_kernel(float* __restrict__ out, int n)
{
    int i = blockIdx.x * blockDim.x + threadIdx.x;
    if (i < n) out[i] = 0.0f;
    cudaTriggerProgrammaticLaunchCompletion();
}

__global__ void __launch_bounds__(THREADS)
epidemic_matvec_kernel(const float* __restrict__ x,
                       const float* __restrict__ A,
                       float* __restrict__ out,
                       int n, int seg_len)
{
    const int tid    = threadIdx.x;
    const int lane   = tid & 31;
    const int warpId = blockIdx.x * WARPS_PER_BLOCK + (tid >> 5);
    if (warpId >= n * SEG) return;

    const int row = warpId >> 3;        // warpId / SEG
    const int seg = warpId & (SEG - 1); // warpId % SEG
    const int j0  = seg * seg_len;
    const int j1  = min(n, j0 + seg_len);
    if (j0 >= n) return;

    const float* __restrict__ Arow = A + (size_t)row * (size_t)n;

    float s0 = 0.0f, s1 = 0.0f, s2 = 0.0f, s3 = 0.0f;

    if ((n & 3) == 0) {
        // seg_len is a multiple of 8 -> segment bases stay 32B-aligned
        const float4* __restrict__ A4 = reinterpret_cast<const float4*>(Arow + j0);
        const float4* __restrict__ x4 = reinterpret_cast<const float4*>(x + j0);
        const int nv = (j1 - j0) >> 2;

        int k = lane;
        // Front-batch 8 independent streaming LDG.128 on A (MLP=8, 4 KB).
        for (; k + 224 < nv; k += 256) {
            float4 a0 = __ldcs(&A4[k]);
            float4 a1 = __ldcs(&A4[k + 32]);
            float4 a2 = __ldcs(&A4[k + 64]);
            float4 a3 = __ldcs(&A4[k + 96]);
            float4 a4 = __ldcs(&A4[k + 128]);
            float4 a5 = __ldcs(&A4[k + 160]);
            float4 a6 = __ldcs(&A4[k + 192]);
            float4 a7 = __ldcs(&A4[k + 224]);
            float4 b0 = x4[k];
            float4 b1 = x4[k + 32];
            float4 b2 = x4[k + 64];
            float4 b3 = x4[k + 96];
            float4 b4 = x4[k + 128];
            float4 b5 = x4[k + 160];
            float4 b6 = x4[k + 192];
            float4 b7 = x4[k + 224];
            s0 += a0.x * (1.0f - b0.x) + a0.y * (1.0f - b0.y)
                + a0.z * (1.0f - b0.z) + a0.w * (1.0f - b0.w);
            s1 += a1.x * (1.0f - b1.x) + a1.y * (1.0f - b1.y)
                + a1.z * (1.0f - b1.z) + a1.w * (1.0f - b1.w);
            s2 += a2.x * (1.0f - b2.x) + a2.y * (1.0f - b2.y)
                + a2.z * (1.0f - b2.z) + a2.w * (1.0f - b2.w);
            s3 += a3.x * (1.0f - b3.x) + a3.y * (1.0f - b3.y)
                + a3.z * (1.0f - b3.z) + a3.w * (1.0f - b3.w);
            s0 += a4.x * (1.0f - b4.x) + a4.y * (1.0f - b4.y)
                + a4.z * (1.0f - b4.z) + a4.w * (1.0f - b4.w);
            s1 += a5.x * (1.0f - b5.x) + a5.y * (1.0f - b5.y)
                + a5.z * (1.0f - b5.z) + a5.w * (1.0f - b5.w);
            s2 += a6.x * (1.0f - b6.x) + a6.y * (1.0f - b6.y)
                + a6.z * (1.0f - b6.z) + a6.w * (1.0f - b6.w);
            s3 += a7.x * (1.0f - b7.x) + a7.y * (1.0f - b7.y)
                + a7.z * (1.0f - b7.z) + a7.w * (1.0f - b7.w);
        }
        // MLP=4 cleanup
        for (; k + 96 < nv; k += 128) {
            float4 a0 = __ldcs(&A4[k]);
            float4 a1 = __ldcs(&A4[k + 32]);
            float4 a2 = __ldcs(&A4[k + 64]);
            float4 a3 = __ldcs(&A4[k + 96]);
            float4 b0 = x4[k];
            float4 b1 = x4[k + 32];
            float4 b2 = x4[k + 64];
            float4 b3 = x4[k + 96];
            s0 += a0.x * (1.0f - b0.x) + a0.y * (1.0f - b0.y)
                + a0.z * (1.0f - b0.z) + a0.w * (1.0f - b0.w);
            s1 += a1.x * (1.0f - b1.x) + a1.y * (1.0f - b1.y)
                + a1.z * (1.0f - b1.z) + a1.w * (1.0f - b1.w);
            s2 += a2.x * (1.0f - b2.x) + a2.y * (1.0f - b2.y)
                + a2.z * (1.0f - b2.z) + a2.w * (1.0f - b2.w);
            s3 += a3.x * (1.0f - b3.x) + a3.y * (1.0f - b3.y)
                + a3.z * (1.0f - b3.z) + a3.w * (1.0f - b3.w);
        }
        for (; k < nv; k += 32) {
            float4 a0 = __ldcs(&A4[k]);
            float4 b0 = x4[k];
            s0 += a0.x * (1.0f - b0.x) + a0.y * (1.0f - b0.y)
                + a0.z * (1.0f - b0.z) + a0.w * (1.0f - b0.w);
        }
        // scalar remainder within segment
        for (int j = j0 + (nv << 2) + lane; j < j1; j += 32)
            s0 += Arow[j] * (1.0f - x[j]);
    } else {
        // general scalar fallback
        for (int j = j0 + lane; j < j1; j += 32)
            s0 += Arow[j] * (1.0f - x[j]);
    }

    float sum = (s0 + s1) + (s2 + s3);
    #pragma unroll
    for (int off = 16; off > 0; off >>= 1)
        sum += __shfl_xor_sync(0xFFFFFFFFu, sum, off);

    if (lane == 0) {
        // init kernel must have finished zeroing out[] before the RMW;
        // all streaming above overlapped with it under PDL.
        cudaGridDependencySynchronize();
        atomicAdd(&out[row], 0.1f * x[row] * sum);
    }
}

extern "C" void kernel_launch(void* const* d_in, const int* in_sizes, int n_in,
                              void* d_out, int out_size)
{
    // metadata order: t (unused), x [n], A [n*n]
    const float* x = (const float*)d_in[1];
    const float* A = (const float*)d_in[2];
    float* out     = (float*)d_out;
    const int n    = in_sizes[1];

    // zero the accumulator output
    init_out_kernel<<<(n + 255) / 256, 256>>>(out, n);

    // seg_len: multiple of 8 so segment bases stay 32B-aligned
    int seg_len = (n + SEG - 1) / SEG;
    seg_len = (seg_len + 7) & ~7;

    const long long total_warps = (long long)n * SEG;
    const int blocks = (int)((total_warps + WARPS_PER_BLOCK - 1) / WARPS_PER_BLOCK);

    cudaLaunchConfig_t cfg = {};
    cfg.gridDim  = dim3((unsigned)blocks, 1, 1);
    cfg.blockDim = dim3(THREADS, 1, 1);
    cfg.dynamicSmemBytes = 0;
    cfg.stream = 0;
    cudaLaunchAttribute attrs[1];
    attrs[0].id = cudaLaunchAttributeProgrammaticStreamSerialization;
    attrs[0].val.programmaticStreamSerializationAllowed = 1;
    cfg.attrs = attrs;
    cfg.numAttrs = 1;

    cudaLaunchKernelEx(&cfg, epidemic_matvec_kernel, x, A, out, n, seg_len);
}

// round 17
// speedup vs baseline: 1.2000x; 1.2000x over previous
#include <cuda_runtime.h>
#include <cuda_bf16.h>
#include <cstdint>

// out[i] = 0.1 * x[i] * sum_j A[i][j] * (1 - x[j])
// HBM-bound fp32 matvec. A (1 GiB) streamed once with evict-first LDG.128.
// K-split SEG=8: one warp per (row, 1/8-row segment) -> 8 KB tasks (proven
// sweet spot), MLP=8 front-batched loads. 128-thread CTAs (4 warps): finer
// scheduling granularity (32 KB/CTA), ~9 CTAs/SM -> ~36 warps resident.
// Independent warp exits + atomicAdd; zero-init overlapped via PDL.

#define WARPS_PER_BLOCK 4
#define THREADS (WARPS_PER_BLOCK * 32)
#define SEG 8

__global__ void init_out_kernel(float* __restrict__ out, int n)
{
    int i = blockIdx.x * blockDim.x + threadIdx.x;
    if (i < n) out[i] = 0.0f;
    cudaTriggerProgrammaticLaunchCompletion();
}

__global__ void __launch_bounds__(THREADS)
epidemic_matvec_kernel(const float* __restrict__ x,
                       const float* __restrict__ A,
                       float* __restrict__ out,
                       int n, int seg_len)
{
    const int tid    = threadIdx.x;
    const int lane   = tid & 31;
    const int warpId = blockIdx.x * WARPS_PER_BLOCK + (tid >> 5);
    if (warpId >= n * SEG) return;

    const int row = warpId >> 3;        // warpId / SEG
    const int seg = warpId & (SEG - 1); // warpId % SEG
    const int j0  = seg * seg_len;
    const int j1  = min(n, j0 + seg_len);
    if (j0 >= n) return;

    const float* __restrict__ Arow = A + (size_t)row * (size_t)n;

    float s0 = 0.0f, s1 = 0.0f, s2 = 0.0f, s3 = 0.0f;

    if ((n & 3) == 0) {
        // seg_len is a multiple of 8 -> segment bases stay 32B-aligned
        const float4* __restrict__ A4 = reinterpret_cast<const float4*>(Arow + j0);
        const float4* __restrict__ x4 = reinterpret_cast<const float4*>(x + j0);
        const int nv = (j1 - j0) >> 2;

        int k = lane;
        // Front-batch 8 independent streaming LDG.128 on A (MLP=8, 4 KB).
        for (; k + 224 < nv; k += 256) {
            float4 a0 = __ldcs(&A4[k]);
            float4 a1 = __ldcs(&A4[k + 32]);
            float4 a2 = __ldcs(&A4[k + 64]);
            float4 a3 = __ldcs(&A4[k + 96]);
            float4 a4 = __ldcs(&A4[k + 128]);
            float4 a5 = __ldcs(&A4[k + 160]);
            float4 a6 = __ldcs(&A4[k + 192]);
            float4 a7 = __ldcs(&A4[k + 224]);
            float4 b0 = x4[k];
            float4 b1 = x4[k + 32];
            float4 b2 = x4[k + 64];
            float4 b3 = x4[k + 96];
            float4 b4 = x4[k + 128];
            float4 b5 = x4[k + 160];
            float4 b6 = x4[k + 192];
            float4 b7 = x4[k + 224];
            s0 += a0.x * (1.0f - b0.x) + a0.y * (1.0f - b0.y)
                + a0.z * (1.0f - b0.z) + a0.w * (1.0f - b0.w);
            s1 += a1.x * (1.0f - b1.x) + a1.y * (1.0f - b1.y)
                + a1.z * (1.0f - b1.z) + a1.w * (1.0f - b1.w);
            s2 += a2.x * (1.0f - b2.x) + a2.y * (1.0f - b2.y)
                + a2.z * (1.0f - b2.z) + a2.w * (1.0f - b2.w);
            s3 += a3.x * (1.0f - b3.x) + a3.y * (1.0f - b3.y)
                + a3.z * (1.0f - b3.z) + a3.w * (1.0f - b3.w);
            s0 += a4.x * (1.0f - b4.x) + a4.y * (1.0f - b4.y)
                + a4.z * (1.0f - b4.z) + a4.w * (1.0f - b4.w);
            s1 += a5.x * (1.0f - b5.x) + a5.y * (1.0f - b5.y)
                + a5.z * (1.0f - b5.z) + a5.w * (1.0f - b5.w);
            s2 += a6.x * (1.0f - b6.x) + a6.y * (1.0f - b6.y)
                + a6.z * (1.0f - b6.z) + a6.w * (1.0f - b6.w);
            s3 += a7.x * (1.0f - b7.x) + a7.y * (1.0f - b7.y)
                + a7.z * (1.0f - b7.z) + a7.w * (1.0f - b7.w);
        }
        // MLP=4 cleanup
        for (; k + 96 < nv; k += 128) {
            float4 a0 = __ldcs(&A4[k]);
            float4 a1 = __ldcs(&A4[k + 32]);
            float4 a2 = __ldcs(&A4[k + 64]);
            float4 a3 = __ldcs(&A4[k + 96]);
            float4 b0 = x4[k];
            float4 b1 = x4[k + 32];
            float4 b2 = x4[k + 64];
            float4 b3 = x4[k + 96];
            s0 += a0.x * (1.0f - b0.x) + a0.y * (1.0f - b0.y)
                + a0.z * (1.0f - b0.z) + a0.w * (1.0f - b0.w);
            s1 += a1.x * (1.0f - b1.x) + a1.y * (1.0f - b1.y)
                + a1.z * (1.0f - b1.z) + a1.w * (1.0f - b1.w);
            s2 += a2.x * (1.0f - b2.x) + a2.y * (1.0f - b2.y)
                + a2.z * (1.0f - b2.z) + a2.w * (1.0f - b2.w);
            s3 += a3.x * (1.0f - b3.x) + a3.y * (1.0f - b3.y)
                + a3.z * (1.0f - b3.z) + a3.w * (1.0f - b3.w);
        }
        for (; k < nv; k += 32) {
            float4 a0 = __ldcs(&A4[k]);
            float4 b0 = x4[k];
            s0 += a0.x * (1.0f - b0.x) + a0.y * (1.0f - b0.y)
                + a0.z * (1.0f - b0.z) + a0.w * (1.0f - b0.w);
        }
        // scalar remainder within segment
        for (int j = j0 + (nv << 2) + lane; j < j1; j += 32)
            s0 += Arow[j] * (1.0f - x[j]);
    } else {
        // general scalar fallback
        for (int j = j0 + lane; j < j1; j += 32)
            s0 += Arow[j] * (1.0f - x[j]);
    }

    float sum = (s0 + s1) + (s2 + s3);
    #pragma unroll
    for (int off = 16; off > 0; off >>= 1)
        sum += __shfl_xor_sync(0xFFFFFFFFu, sum, off);

    if (lane == 0) {
        // init kernel must have finished zeroing out[] before the RMW;
        // all streaming above overlapped with it under PDL.
        cudaGridDependencySynchronize();
        atomicAdd(&out[row], 0.1f * x[row] * sum);
    }
}

extern "C" void kernel_launch(void* const* d_in, const int* in_sizes, int n_in,
                              void* d_out, int out_size)
{
    // metadata order: t (unused), x [n], A [n*n]
    const float* x = (const float*)d_in[1];
    const float* A = (const float*)d_in[2];
    float* out     = (float*)d_out;
    const int n    = in_sizes[1];

    // zero the accumulator output
    init_out_kernel<<<(n + 255) / 256, 256>>>(out, n);

    // seg_len: multiple of 8 so segment bases stay 32B-aligned
    int seg_len = (n + SEG - 1) / SEG;
    seg_len = (seg_len + 7) & ~7;

    const long long total_warps = (long long)n * SEG;
    const int blocks = (int)((total_warps + WARPS_PER_BLOCK - 1) / WARPS_PER_BLOCK);

    cudaLaunchConfig_t cfg = {};
    cfg.gridDim  = dim3((unsigned)blocks, 1, 1);
    cfg.blockDim = dim3(THREADS, 1, 1);
    cfg.dynamicSmemBytes = 0;
    cfg.stream = 0;
    cudaLaunchAttribute attrs[1];
    attrs[0].id = cudaLaunchAttributeProgrammaticStreamSerialization;
    attrs[0].val.programmaticStreamSerializationAllowed = 1;
    cfg.attrs = attrs;
    cfg.numAttrs = 1;

    cudaLaunchKernelEx(&cfg, epidemic_matvec_kernel, x, A, out, n, seg_len);
}